// round 1
// baseline (speedup 1.0000x reference)
#include <cuda_runtime.h>
#include <math.h>

#define NTOK 4096
#define DDIM 512
#define HDIM 2048
#define NEXP 8
#define NC 7
#define BETA_FIXED (1.0f/3.0f)
#define BETA_DYN   (2.0f/3.0f)

// ---------------- scratch (static device globals; no allocation) ----------------
__device__ float g_H[(size_t)NEXP * NTOK * HDIM];   // 256 MB: hidden activations per segment row
__device__ float g_Y[(size_t)NEXP * NTOK * DDIM];   // 64 MB: scaled expert outputs per segment row
__device__ int   g_list[NEXP * NTOK];               // segment row -> token id (dynamic experts)
__device__ float g_scale[NEXP * NTOK];              // segment row -> output scale (dynamic experts)
__device__ int   g_pos[NTOK * 2];                   // token -> 2 dynamic global row ids
__device__ int   g_cnt[NEXP];                       // per-expert token counts (0 unused semantics for e=0)
__device__ float g_imp[NC];                         // softmax-prob sums for importance

// ---------------- init ----------------
__global__ void k_init() {
    int t = threadIdx.x;
    if (t < NEXP) g_cnt[t] = 0;
    if (t < NC)   g_imp[t] = 0.f;
}

// ---------------- router: logits, top-2, gates, gather lists, importance ----------------
__global__ void k_router(const float* __restrict__ x,
                         const float* __restrict__ rW,
                         const float* __restrict__ rb,
                         float* __restrict__ out, long out_size) {
    __shared__ float imp_s[NC];
    int t = threadIdx.x;
    if (t < NC) imp_s[t] = 0.f;
    __syncthreads();

    int w = t >> 5, lane = t & 31;
    int n = blockIdx.x * 8 + w;   // warp per token

    float acc[NC];
#pragma unroll
    for (int j = 0; j < NC; j++) acc[j] = 0.f;

    const float* xr = x + (size_t)n * DDIM;
    for (int k = lane; k < DDIM; k += 32) {
        float xv = xr[k];
        const float* wr = rW + (size_t)k * NC;
#pragma unroll
        for (int j = 0; j < NC; j++) acc[j] += xv * wr[j];
    }
#pragma unroll
    for (int j = 0; j < NC; j++) {
#pragma unroll
        for (int off = 16; off > 0; off >>= 1)
            acc[j] += __shfl_xor_sync(0xffffffffu, acc[j], off);
        acc[j] += rb[j];
    }

    if (lane == 0) {
        // full softmax for importance
        float m = acc[0];
#pragma unroll
        for (int j = 1; j < NC; j++) m = fmaxf(m, acc[j]);
        float p[NC], s = 0.f;
#pragma unroll
        for (int j = 0; j < NC; j++) { p[j] = __expf(acc[j] - m); s += p[j]; }
        float inv = 1.f / s;
#pragma unroll
        for (int j = 0; j < NC; j++) atomicAdd(&imp_s[j], p[j] * inv);

        // top-2 (lowest index wins ties, matching lax.top_k)
        int i1 = 0;
#pragma unroll
        for (int j = 1; j < NC; j++) if (acc[j] > acc[i1]) i1 = j;
        int i2 = (i1 == 0) ? 1 : 0;
#pragma unroll
        for (int j = 0; j < NC; j++) if (j != i1 && acc[j] > acc[i2]) i2 = j;

        float v1 = acc[i1], v2 = acc[i2];
        float e2 = __expf(v2 - v1);
        float den = 1.f / (1.f + e2);
        float gA = den;            // gate for top-1
        float gB = e2 * den;       // gate for top-2

        int eA = i1 + 1, eB = i2 + 1;
        int rA = atomicAdd(&g_cnt[eA], 1);
        int rB = atomicAdd(&g_cnt[eB], 1);
        int rowA = eA * NTOK + rA;
        int rowB = eB * NTOK + rB;
        g_list[rowA] = n;  g_list[rowB] = n;
        g_scale[rowA] = BETA_DYN * gA;
        g_scale[rowB] = BETA_DYN * gB;
        g_pos[2 * n]     = rowA;
        g_pos[2 * n + 1] = rowB;

        long selbase = (long)NTOK * DDIM + 2;
        if (selbase + 2 * (long)NTOK <= out_size) {
            out[selbase + 2 * n]     = (float)eA;
            out[selbase + 2 * n + 1] = (float)eB;
        }
    }
    __syncthreads();
    if (t < NC) atomicAdd(&g_imp[t], imp_s[t]);
}

// ---------------- aux losses ----------------
__global__ void k_aux(float* __restrict__ out, long out_size) {
    float lbl = 0.f, ent = 0.f;
#pragma unroll
    for (int j = 0; j < NC; j++) {
        float imp = g_imp[j] / (float)NTOK;
        float d = imp - (1.0f / NC);
        lbl += d * d;
        float c = fmaxf(imp, 1e-8f);
        ent -= imp * logf(c);
    }
    lbl *= (1.0f / NC);
    long base = (long)NTOK * DDIM;
    if (base < out_size)     out[base]     = lbl;
    if (base + 1 < out_size) out[base + 1] = ent;
}

// ---------------- GEMM pass A: H = relu(Xg @ W1[e] + b1[e]) ----------------
// 128x128 tile, 256 threads, 8x8 per thread, K-step 8.
__global__ void __launch_bounds__(256) k_gemm1(
    const float* __restrict__ x, const float* __restrict__ W1,
    const float* __restrict__ b1)
{
    int s = blockIdx.z;
    int cnt = (s == 0) ? NTOK : g_cnt[s];
    int m0 = blockIdx.x * 128;
    if (m0 >= cnt) return;
    int n0 = blockIdx.y * 128;

    __shared__ float As[8][132];
    __shared__ float Bs[8][132];
    __shared__ int   toks[128];

    int t = threadIdx.x;
    if (t < 128) {
        int m = m0 + t;
        toks[t] = (m < cnt) ? ((s == 0) ? m : g_list[s * NTOK + m]) : 0;
    }
    __syncthreads();

    const float* Wb = W1 + (size_t)s * DDIM * HDIM + n0;

    int tr = (t >> 4) << 3;
    int tc = (t & 15) << 3;
    int a_m = t >> 1;
    int a_k = (t & 1) << 2;
    int b_k = t >> 5;
    int b_h = (t & 31) << 2;

    const float* arow = x + (size_t)toks[a_m] * DDIM + a_k;

    float acc[8][8];
#pragma unroll
    for (int i = 0; i < 8; i++)
#pragma unroll
        for (int j = 0; j < 8; j++) acc[i][j] = 0.f;

    for (int k0 = 0; k0 < DDIM; k0 += 8) {
        float4 av = *(const float4*)(arow + k0);
        float4 bv = *(const float4*)(Wb + (size_t)(k0 + b_k) * HDIM + b_h);
        As[a_k + 0][a_m] = av.x; As[a_k + 1][a_m] = av.y;
        As[a_k + 2][a_m] = av.z; As[a_k + 3][a_m] = av.w;
        *(float4*)&Bs[b_k][b_h] = bv;
        __syncthreads();
#pragma unroll
        for (int kk = 0; kk < 8; kk++) {
            float a[8], b[8];
            *(float4*)&a[0] = *(const float4*)&As[kk][tr];
            *(float4*)&a[4] = *(const float4*)&As[kk][tr + 4];
            *(float4*)&b[0] = *(const float4*)&Bs[kk][tc];
            *(float4*)&b[4] = *(const float4*)&Bs[kk][tc + 4];
#pragma unroll
            for (int i = 0; i < 8; i++)
#pragma unroll
                for (int j = 0; j < 8; j++)
                    acc[i][j] = fmaf(a[i], b[j], acc[i][j]);
        }
        __syncthreads();
    }

    float bb[8];
    *(float4*)&bb[0] = *(const float4*)(b1 + (size_t)s * HDIM + n0 + tc);
    *(float4*)&bb[4] = *(const float4*)(b1 + (size_t)s * HDIM + n0 + tc + 4);

#pragma unroll
    for (int i = 0; i < 8; i++) {
        int m = m0 + tr + i;
        if (m < cnt) {
            float* hrow = g_H + ((size_t)s * NTOK + m) * HDIM + n0 + tc;
            float4 v0, v1;
            v0.x = fmaxf(acc[i][0] + bb[0], 0.f);
            v0.y = fmaxf(acc[i][1] + bb[1], 0.f);
            v0.z = fmaxf(acc[i][2] + bb[2], 0.f);
            v0.w = fmaxf(acc[i][3] + bb[3], 0.f);
            v1.x = fmaxf(acc[i][4] + bb[4], 0.f);
            v1.y = fmaxf(acc[i][5] + bb[5], 0.f);
            v1.z = fmaxf(acc[i][6] + bb[6], 0.f);
            v1.w = fmaxf(acc[i][7] + bb[7], 0.f);
            *(float4*)hrow       = v0;
            *(float4*)(hrow + 4) = v1;
        }
    }
}

// ---------------- GEMM pass B: Y = scale_row * (H @ W2[e] + b2[e]) ----------------
__global__ void __launch_bounds__(256) k_gemm2(
    const float* __restrict__ W2, const float* __restrict__ b2,
    const float* __restrict__ fixed_w)
{
    int s = blockIdx.z;
    int cnt = (s == 0) ? NTOK : g_cnt[s];
    int m0 = blockIdx.x * 128;
    if (m0 >= cnt) return;
    int n0 = blockIdx.y * 128;

    __shared__ float As[8][132];
    __shared__ float Bs[8][132];
    __shared__ float scl[128];

    int t = threadIdx.x;
    if (t < 128) {
        int m = m0 + t;
        float sc = 0.f;
        if (m < cnt) sc = (s == 0) ? (BETA_FIXED * fixed_w[0]) : g_scale[s * NTOK + m];
        scl[t] = sc;
    }
    __syncthreads();

    const float* Ab = g_H + ((size_t)s * NTOK + m0) * HDIM;
    const float* Wb = W2 + (size_t)s * HDIM * DDIM + n0;

    int tr = (t >> 4) << 3;
    int tc = (t & 15) << 3;
    int a_m = t >> 1;
    int a_k = (t & 1) << 2;
    int b_k = t >> 5;
    int b_h = (t & 31) << 2;

    float acc[8][8];
#pragma unroll
    for (int i = 0; i < 8; i++)
#pragma unroll
        for (int j = 0; j < 8; j++) acc[i][j] = 0.f;

    for (int k0 = 0; k0 < HDIM; k0 += 8) {
        float4 av = *(const float4*)(Ab + (size_t)a_m * HDIM + k0 + a_k);
        float4 bv = *(const float4*)(Wb + (size_t)(k0 + b_k) * DDIM + b_h);
        As[a_k + 0][a_m] = av.x; As[a_k + 1][a_m] = av.y;
        As[a_k + 2][a_m] = av.z; As[a_k + 3][a_m] = av.w;
        *(float4*)&Bs[b_k][b_h] = bv;
        __syncthreads();
#pragma unroll
        for (int kk = 0; kk < 8; kk++) {
            float a[8], b[8];
            *(float4*)&a[0] = *(const float4*)&As[kk][tr];
            *(float4*)&a[4] = *(const float4*)&As[kk][tr + 4];
            *(float4*)&b[0] = *(const float4*)&Bs[kk][tc];
            *(float4*)&b[4] = *(const float4*)&Bs[kk][tc + 4];
#pragma unroll
            for (int i = 0; i < 8; i++)
#pragma unroll
                for (int j = 0; j < 8; j++)
                    acc[i][j] = fmaf(a[i], b[j], acc[i][j]);
        }
        __syncthreads();
    }

    float bb[8];
    *(float4*)&bb[0] = *(const float4*)(b2 + (size_t)s * DDIM + n0 + tc);
    *(float4*)&bb[4] = *(const float4*)(b2 + (size_t)s * DDIM + n0 + tc + 4);

#pragma unroll
    for (int i = 0; i < 8; i++) {
        int m = m0 + tr + i;
        if (m < cnt) {
            float sc = scl[tr + i];
            float* yrow = g_Y + ((size_t)s * NTOK + m) * DDIM + n0 + tc;
            float4 v0, v1;
            v0.x = (acc[i][0] + bb[0]) * sc;
            v0.y = (acc[i][1] + bb[1]) * sc;
            v0.z = (acc[i][2] + bb[2]) * sc;
            v0.w = (acc[i][3] + bb[3]) * sc;
            v1.x = (acc[i][4] + bb[4]) * sc;
            v1.y = (acc[i][5] + bb[5]) * sc;
            v1.z = (acc[i][6] + bb[6]) * sc;
            v1.w = (acc[i][7] + bb[7]) * sc;
            *(float4*)yrow       = v0;
            *(float4*)(yrow + 4) = v1;
        }
    }
}

// ---------------- combine: out[n] = Y_fixed[n] + Y_dynA + Y_dynB ----------------
__global__ void k_combine(float* __restrict__ out) {
    int n = blockIdx.x;
    int t = threadIdx.x;  // 128 threads, float4 each = 512 floats
    const float4* y0 = (const float4*)(g_Y + (size_t)n * DDIM);
    int pA = g_pos[2 * n], pB = g_pos[2 * n + 1];
    const float4* yA = (const float4*)(g_Y + (size_t)pA * DDIM);
    const float4* yB = (const float4*)(g_Y + (size_t)pB * DDIM);
    float4 a = y0[t], b = yA[t], c = yB[t];
    float4 r;
    r.x = a.x + b.x + c.x;
    r.y = a.y + b.y + c.y;
    r.z = a.z + b.z + c.z;
    r.w = a.w + b.w + c.w;
    ((float4*)(out + (size_t)n * DDIM))[t] = r;
}

// ---------------- launch ----------------
extern "C" void kernel_launch(void* const* d_in, const int* in_sizes, int n_in,
                              void* d_out, int out_size) {
    const float* x  = (const float*)d_in[0];
    const float* rW = (const float*)d_in[1];
    const float* rb = (const float*)d_in[2];
    const float* W1 = (const float*)d_in[3];
    const float* b1 = (const float*)d_in[4];
    const float* W2 = (const float*)d_in[5];
    const float* b2 = (const float*)d_in[6];
    const float* fw = (const float*)d_in[7];
    float* out = (float*)d_out;
    long osz = (long)out_size;

    k_init<<<1, 32>>>();
    k_router<<<NTOK / 8, 256>>>(x, rW, rb, out, osz);
    k_aux<<<1, 1>>>(out, osz);
    k_gemm1<<<dim3(32, 16, 8), 256>>>(x, W1, b1);
    k_gemm2<<<dim3(32, 4, 8), 256>>>(W2, b2, fw);
    k_combine<<<NTOK, 128>>>(out);
}

// round 3
// speedup vs baseline: 2.2544x; 2.2544x over previous
#include <cuda_runtime.h>
#include <cuda_bf16.h>
#include <math.h>
#include <cstdint>

#define NTOK 4096
#define DDIM 512
#define HDIM 2048
#define NEXP 8
#define NC 7
#define BETA_FIXED (1.0f/3.0f)
#define BETA_DYN   (2.0f/3.0f)

// ================= scratch (static device globals) =================
__device__ __nv_bfloat16 g_xh[NTOK * DDIM];
__device__ __nv_bfloat16 g_xl[NTOK * DDIM];
__device__ __nv_bfloat16 g_w1h[NEXP * HDIM * DDIM];   // [E][H][D]  (K-major gemm1 B)
__device__ __nv_bfloat16 g_w1l[NEXP * HDIM * DDIM];
__device__ __nv_bfloat16 g_w2h[NEXP * DDIM * HDIM];   // [E][D][H]  (K-major gemm2 B)
__device__ __nv_bfloat16 g_w2l[NEXP * DDIM * HDIM];
__device__ __nv_bfloat16 g_hh[(size_t)NEXP * NTOK * HDIM];  // hidden split-bf16 hi
__device__ __nv_bfloat16 g_hl[(size_t)NEXP * NTOK * HDIM];  // hidden split-bf16 lo
__device__ float g_Y[(size_t)NEXP * NTOK * DDIM];
__device__ int   g_list[NEXP * NTOK];
__device__ float g_scale[NEXP * NTOK];
__device__ int   g_pos[NTOK * 2];
__device__ int   g_cnt[NEXP];
__device__ float g_imp[NC];

// ================= helpers =================
__device__ __forceinline__ uint32_t smem_u32(const void* p) {
    uint32_t a;
    asm("{ .reg .u64 t; cvta.to.shared.u64 t, %1; cvt.u32.u64 %0, t; }" : "=r"(a) : "l"(p));
    return a;
}
__device__ __forceinline__ void cpa16(uint32_t dst, const void* src) {
    asm volatile("cp.async.cg.shared.global [%0], [%1], 16;" :: "r"(dst), "l"(src));
}
#define CPA_COMMIT() asm volatile("cp.async.commit_group;" ::: "memory")
#define CPA_WAIT0()  asm volatile("cp.async.wait_group 0;" ::: "memory")

__device__ __forceinline__ void ldm_x4(uint32_t addr, uint32_t* r) {
    asm volatile("ldmatrix.sync.aligned.m8n8.x4.shared.b16 {%0,%1,%2,%3}, [%4];"
        : "=r"(r[0]), "=r"(r[1]), "=r"(r[2]), "=r"(r[3]) : "r"(addr));
}
__device__ __forceinline__ void mma16816(float* c, const uint32_t* a, uint32_t b0, uint32_t b1) {
    asm volatile("mma.sync.aligned.m16n8k16.row.col.f32.bf16.bf16.f32 "
        "{%0,%1,%2,%3}, {%4,%5,%6,%7}, {%8,%9}, {%0,%1,%2,%3};"
        : "+f"(c[0]), "+f"(c[1]), "+f"(c[2]), "+f"(c[3])
        : "r"(a[0]), "r"(a[1]), "r"(a[2]), "r"(a[3]), "r"(b0), "r"(b1));
}
__device__ __forceinline__ void split2(float v, __nv_bfloat16& h, __nv_bfloat16& l) {
    h = __float2bfloat16(v);
    l = __float2bfloat16(v - __bfloat162float(h));
}
__device__ __forceinline__ uint32_t pack2(__nv_bfloat16 a, __nv_bfloat16 b) {
    return ((uint32_t)__bfloat16_as_ushort(b) << 16) | __bfloat16_as_ushort(a);
}

// smem tile layout (per stage): Ah | Al | Bh | Bl, each 128 rows x 144B (72 bf16, k-chunk 64 + 8 pad)
#define RSB 144
#define HALF_BYTES (128 * RSB)        // 18432
#define OFF_AH 0
#define OFF_AL (1 * HALF_BYTES)
#define OFF_BH (2 * HALF_BYTES)
#define OFF_BL (3 * HALF_BYTES)
#define STAGE_BYTES (4 * HALF_BYTES)  // 73728
#define SM_TILES 1024                 // aux region first
#define SMEM_BYTES (SM_TILES + 2 * STAGE_BYTES)   // 148480

// ================= init =================
__global__ void k_init() {
    int t = threadIdx.x;
    if (t < NEXP) g_cnt[t] = 0;
    if (t < NC)   g_imp[t] = 0.f;
}

// ================= router =================
__global__ void k_router(const float* __restrict__ x,
                         const float* __restrict__ rW,
                         const float* __restrict__ rb,
                         float* __restrict__ out, long out_size) {
    __shared__ float imp_s[NC];
    int t = threadIdx.x;
    if (t < NC) imp_s[t] = 0.f;
    __syncthreads();

    int w = t >> 5, lane = t & 31;
    int n = blockIdx.x * 8 + w;

    float acc[NC];
#pragma unroll
    for (int j = 0; j < NC; j++) acc[j] = 0.f;

    const float* xr = x + (size_t)n * DDIM;
    for (int k = lane; k < DDIM; k += 32) {
        float xv = xr[k];
        const float* wr = rW + (size_t)k * NC;
#pragma unroll
        for (int j = 0; j < NC; j++) acc[j] += xv * wr[j];
    }
#pragma unroll
    for (int j = 0; j < NC; j++) {
#pragma unroll
        for (int off = 16; off > 0; off >>= 1)
            acc[j] += __shfl_xor_sync(0xffffffffu, acc[j], off);
        acc[j] += rb[j];
    }

    if (lane == 0) {
        float m = acc[0];
#pragma unroll
        for (int j = 1; j < NC; j++) m = fmaxf(m, acc[j]);
        float p[NC], s = 0.f;
#pragma unroll
        for (int j = 0; j < NC; j++) { p[j] = __expf(acc[j] - m); s += p[j]; }
        float inv = 1.f / s;
#pragma unroll
        for (int j = 0; j < NC; j++) atomicAdd(&imp_s[j], p[j] * inv);

        int i1 = 0;
#pragma unroll
        for (int j = 1; j < NC; j++) if (acc[j] > acc[i1]) i1 = j;
        int i2 = (i1 == 0) ? 1 : 0;
#pragma unroll
        for (int j = 0; j < NC; j++) if (j != i1 && acc[j] > acc[i2]) i2 = j;

        float e2 = __expf(acc[i2] - acc[i1]);
        float den = 1.f / (1.f + e2);
        float gA = den, gB = e2 * den;

        int eA = i1 + 1, eB = i2 + 1;
        int rA = atomicAdd(&g_cnt[eA], 1);
        int rB = atomicAdd(&g_cnt[eB], 1);
        int rowA = eA * NTOK + rA;
        int rowB = eB * NTOK + rB;
        g_list[rowA] = n;  g_list[rowB] = n;
        g_scale[rowA] = BETA_DYN * gA;
        g_scale[rowB] = BETA_DYN * gB;
        g_pos[2 * n]     = rowA;
        g_pos[2 * n + 1] = rowB;

        long selbase = (long)NTOK * DDIM + 2;
        if (selbase + 2 * (long)NTOK <= out_size) {
            out[selbase + 2 * n]     = (float)eA;
            out[selbase + 2 * n + 1] = (float)eB;
        }
    }
    __syncthreads();
    if (t < NC) atomicAdd(&g_imp[t], imp_s[t]);
}

__global__ void k_aux(float* __restrict__ out, long out_size) {
    float lbl = 0.f, ent = 0.f;
#pragma unroll
    for (int j = 0; j < NC; j++) {
        float imp = g_imp[j] / (float)NTOK;
        float d = imp - (1.0f / NC);
        lbl += d * d;
        ent -= imp * logf(fmaxf(imp, 1e-8f));
    }
    lbl *= (1.0f / NC);
    long base = (long)NTOK * DDIM;
    if (base < out_size)     out[base]     = lbl;
    if (base + 1 < out_size) out[base + 1] = ent;
}

// ================= split/transpose conversions =================
__global__ void k_split_x(const float4* __restrict__ x) {
    int i = blockIdx.x * blockDim.x + threadIdx.x;
    float4 v = x[i];
    __nv_bfloat16 h0, h1, h2, h3, l0, l1, l2, l3;
    split2(v.x, h0, l0); split2(v.y, h1, l1);
    split2(v.z, h2, l2); split2(v.w, h3, l3);
    uint2 hh, ll;
    hh.x = pack2(h0, h1); hh.y = pack2(h2, h3);
    ll.x = pack2(l0, l1); ll.y = pack2(l2, l3);
    ((uint2*)g_xh)[i] = hh;
    ((uint2*)g_xl)[i] = ll;
}

// in [E][R][C] f32 -> out [E][C][R] bf16 hi/lo; which: 0=W1, 1=W2
__global__ void k_split_tr(const float* __restrict__ in, int R, int C, int which) {
    __shared__ float tile[32][33];
    int e = blockIdx.z;
    int c0 = blockIdx.x * 32, r0 = blockIdx.y * 32;
    int tx = threadIdx.x, ty = threadIdx.y;   // 32 x 8
    const float* ip = in + (size_t)e * R * C;
#pragma unroll
    for (int i = 0; i < 4; i++)
        tile[ty + 8 * i][tx] = ip[(size_t)(r0 + ty + 8 * i) * C + c0 + tx];
    __syncthreads();
    __nv_bfloat16* oh = which ? g_w2h : g_w1h;
    __nv_bfloat16* ol = which ? g_w2l : g_w1l;
#pragma unroll
    for (int i = 0; i < 4; i++) {
        float v = tile[tx][ty + 8 * i];
        __nv_bfloat16 h, l;
        split2(v, h, l);
        size_t o = ((size_t)e * C + c0 + ty + 8 * i) * R + r0 + tx;
        oh[o] = h; ol[o] = l;
    }
}

// ================= shared GEMM compute core =================
// block 128x128, 8 warps (2Mx4N), warp tile 64x32, k-chunk 64 (4 x k16)
struct Frag { float a[4][4][4]; };   // acc[mi][ni][4]

__device__ __forceinline__ void gemm_compute_chunk(
    uint32_t tb, int wm, int wn, int lane, float acc[4][4][4])
{
    uint32_t a_row = (uint32_t)((lane & 7) + ((lane >> 3) & 1) * 8);
    uint32_t a_kh  = (uint32_t)(lane >> 4);
    uint32_t a_base_h = tb + OFF_AH + (wm * 64 + a_row) * RSB + a_kh * 16;
    uint32_t a_base_l = tb + OFF_AL + (wm * 64 + a_row) * RSB + a_kh * 16;
    uint32_t b_base_h = tb + OFF_BH + (wn * 32 + lane) * RSB;
    uint32_t b_base_l = tb + OFF_BL + (wn * 32 + lane) * RSB;

#pragma unroll
    for (int kk = 0; kk < 4; kk++) {
        uint32_t ah[4][4], al[4][4];
#pragma unroll
        for (int mf = 0; mf < 4; mf++) {
            ldm_x4(a_base_h + mf * 16 * RSB + kk * 32, ah[mf]);
            ldm_x4(a_base_l + mf * 16 * RSB + kk * 32, al[mf]);
        }
        uint32_t bh0[4], bh1[4], bl0[4], bl1[4];
        ldm_x4(b_base_h + kk * 32,      bh0);
        ldm_x4(b_base_h + kk * 32 + 16, bh1);
        ldm_x4(b_base_l + kk * 32,      bl0);
        ldm_x4(b_base_l + kk * 32 + 16, bl1);

#pragma unroll
        for (int mi = 0; mi < 4; mi++)
#pragma unroll
            for (int ni = 0; ni < 4; ni++)
                mma16816(acc[mi][ni], ah[mi], bh0[ni], bh1[ni]);
#pragma unroll
        for (int mi = 0; mi < 4; mi++)
#pragma unroll
            for (int ni = 0; ni < 4; ni++)
                mma16816(acc[mi][ni], ah[mi], bl0[ni], bl1[ni]);
#pragma unroll
        for (int mi = 0; mi < 4; mi++)
#pragma unroll
            for (int ni = 0; ni < 4; ni++)
                mma16816(acc[mi][ni], al[mi], bh0[ni], bh1[ni]);
    }
}

// ================= GEMM 1: H = relu(Xg @ W1[e]^T-layout + b1[e]) -> split bf16 =================
__global__ void __launch_bounds__(256, 1) k_gemm1(const float* __restrict__ b1) {
    int s = blockIdx.z;
    int cnt = (s == 0) ? NTOK : g_cnt[s];
    int m0 = blockIdx.x * 128;
    if (m0 >= cnt) return;
    int n0 = blockIdx.y * 128;

    extern __shared__ char smem[];
    uint32_t sb = smem_u32(smem);
    int t = threadIdx.x;
    int wid = t >> 5, lane = t & 31;
    int wm = wid >> 2, wn = wid & 3;
    int* toks = (int*)smem;

    if (t < 128) {
        int m = m0 + t;
        toks[t] = (m < cnt) ? ((s == 0) ? m : g_list[s * NTOK + m]) : 0;
    }
    __syncthreads();

    auto load_chunk = [&](int st, int k0) {
        uint32_t base = sb + SM_TILES + st * STAGE_BYTES;
#pragma unroll
        for (int i = 0; i < 4; i++) {
            int id = i * 256 + t;          // 0..1023
            int row = id >> 3, seg = id & 7;
            uint32_t d = base + row * RSB + seg * 16;
            size_t aoff = (size_t)toks[row] * DDIM + k0 + seg * 8;
            cpa16(d + OFF_AH, g_xh + aoff);
            cpa16(d + OFF_AL, g_xl + aoff);
            size_t boff = ((size_t)s * HDIM + n0 + row) * DDIM + k0 + seg * 8;
            cpa16(d + OFF_BH, g_w1h + boff);
            cpa16(d + OFF_BL, g_w1l + boff);
        }
        CPA_COMMIT();
    };

    float acc[4][4][4];
#pragma unroll
    for (int mi = 0; mi < 4; mi++)
#pragma unroll
        for (int ni = 0; ni < 4; ni++)
#pragma unroll
            for (int q = 0; q < 4; q++) acc[mi][ni][q] = 0.f;

    load_chunk(0, 0);
    const int CH = DDIM / 64;   // 8
    for (int c = 0; c < CH; c++) {
        CPA_WAIT0();
        __syncthreads();
        if (c + 1 < CH) load_chunk((c + 1) & 1, (c + 1) * 64);
        gemm_compute_chunk(sb + SM_TILES + (c & 1) * STAGE_BYTES, wm, wn, lane, acc);
    }

    // epilogue: bias + relu + split-bf16 store
    const float* bp = b1 + (size_t)s * HDIM;
#pragma unroll
    for (int mi = 0; mi < 4; mi++) {
        int mA = m0 + wm * 64 + mi * 16 + (lane >> 2);
        int mB = mA + 8;
        size_t rA = ((size_t)s * NTOK + mA) * HDIM;
        size_t rB = ((size_t)s * NTOK + mB) * HDIM;
        bool vA = mA < cnt, vB = mB < cnt;
#pragma unroll
        for (int ni = 0; ni < 4; ni++) {
            int col = n0 + wn * 32 + ni * 8 + 2 * (lane & 3);
            float bc0 = __ldg(bp + col), bc1 = __ldg(bp + col + 1);
            if (vA) {
                float v0 = fmaxf(acc[mi][ni][0] + bc0, 0.f);
                float v1 = fmaxf(acc[mi][ni][1] + bc1, 0.f);
                __nv_bfloat16 h0, h1, l0, l1;
                split2(v0, h0, l0); split2(v1, h1, l1);
                *(uint32_t*)(g_hh + rA + col) = pack2(h0, h1);
                *(uint32_t*)(g_hl + rA + col) = pack2(l0, l1);
            }
            if (vB) {
                float v0 = fmaxf(acc[mi][ni][2] + bc0, 0.f);
                float v1 = fmaxf(acc[mi][ni][3] + bc1, 0.f);
                __nv_bfloat16 h0, h1, l0, l1;
                split2(v0, h0, l0); split2(v1, h1, l1);
                *(uint32_t*)(g_hh + rB + col) = pack2(h0, h1);
                *(uint32_t*)(g_hl + rB + col) = pack2(l0, l1);
            }
        }
    }
}

// ================= GEMM 2: Y = scale * (H @ W2[e] + b2[e]) =================
__global__ void __launch_bounds__(256, 1) k_gemm2(const float* __restrict__ b2,
                                                  const float* __restrict__ fw) {
    int s = blockIdx.z;
    int cnt = (s == 0) ? NTOK : g_cnt[s];
    int m0 = blockIdx.x * 128;
    if (m0 >= cnt) return;
    int n0 = blockIdx.y * 128;

    extern __shared__ char smem[];
    uint32_t sb = smem_u32(smem);
    int t = threadIdx.x;
    int wid = t >> 5, lane = t & 31;
    int wm = wid >> 2, wn = wid & 3;
    float* scl = (float*)smem;

    if (t < 128) {
        int m = m0 + t;
        scl[t] = (m < cnt) ? ((s == 0) ? BETA_FIXED * fw[0] : g_scale[s * NTOK + m]) : 0.f;
    }
    __syncthreads();

    auto load_chunk = [&](int st, int k0) {
        uint32_t base = sb + SM_TILES + st * STAGE_BYTES;
#pragma unroll
        for (int i = 0; i < 4; i++) {
            int id = i * 256 + t;
            int row = id >> 3, seg = id & 7;
            uint32_t d = base + row * RSB + seg * 16;
            size_t aoff = ((size_t)s * NTOK + m0 + row) * HDIM + k0 + seg * 8;
            cpa16(d + OFF_AH, g_hh + aoff);
            cpa16(d + OFF_AL, g_hl + aoff);
            size_t boff = ((size_t)s * DDIM + n0 + row) * HDIM + k0 + seg * 8;
            cpa16(d + OFF_BH, g_w2h + boff);
            cpa16(d + OFF_BL, g_w2l + boff);
        }
        CPA_COMMIT();
    };

    float acc[4][4][4];
#pragma unroll
    for (int mi = 0; mi < 4; mi++)
#pragma unroll
        for (int ni = 0; ni < 4; ni++)
#pragma unroll
            for (int q = 0; q < 4; q++) acc[mi][ni][q] = 0.f;

    load_chunk(0, 0);
    const int CH = HDIM / 64;   // 32
    for (int c = 0; c < CH; c++) {
        CPA_WAIT0();
        __syncthreads();
        if (c + 1 < CH) load_chunk((c + 1) & 1, (c + 1) * 64);
        gemm_compute_chunk(sb + SM_TILES + (c & 1) * STAGE_BYTES, wm, wn, lane, acc);
    }

    // epilogue: (acc + bias) * scale, fp32 store
    const float* bp = b2 + (size_t)s * DDIM;
#pragma unroll
    for (int mi = 0; mi < 4; mi++) {
        int mloc = wm * 64 + mi * 16 + (lane >> 2);
        int mA = m0 + mloc, mB = mA + 8;
        float scA = scl[mloc], scB = scl[mloc + 8];
        size_t rA = ((size_t)s * NTOK + mA) * DDIM;
        size_t rB = ((size_t)s * NTOK + mB) * DDIM;
        bool vA = mA < cnt, vB = mB < cnt;
#pragma unroll
        for (int ni = 0; ni < 4; ni++) {
            int col = n0 + wn * 32 + ni * 8 + 2 * (lane & 3);
            float bc0 = __ldg(bp + col), bc1 = __ldg(bp + col + 1);
            if (vA) {
                float2 v;
                v.x = (acc[mi][ni][0] + bc0) * scA;
                v.y = (acc[mi][ni][1] + bc1) * scA;
                *(float2*)(g_Y + rA + col) = v;
            }
            if (vB) {
                float2 v;
                v.x = (acc[mi][ni][2] + bc0) * scB;
                v.y = (acc[mi][ni][3] + bc1) * scB;
                *(float2*)(g_Y + rB + col) = v;
            }
        }
    }
}

// ================= combine =================
__global__ void k_combine(float* __restrict__ out) {
    int n = blockIdx.x;
    int t = threadIdx.x;
    const float4* y0 = (const float4*)(g_Y + (size_t)n * DDIM);
    int pA = g_pos[2 * n], pB = g_pos[2 * n + 1];
    const float4* yA = (const float4*)(g_Y + (size_t)pA * DDIM);
    const float4* yB = (const float4*)(g_Y + (size_t)pB * DDIM);
    float4 a = y0[t], b = yA[t], c = yB[t];
    float4 r;
    r.x = a.x + b.x + c.x;
    r.y = a.y + b.y + c.y;
    r.z = a.z + b.z + c.z;
    r.w = a.w + b.w + c.w;
    ((float4*)(out + (size_t)n * DDIM))[t] = r;
}

// ================= launch =================
extern "C" void kernel_launch(void* const* d_in, const int* in_sizes, int n_in,
                              void* d_out, int out_size) {
    const float* x  = (const float*)d_in[0];
    const float* rW = (const float*)d_in[1];
    const float* rb = (const float*)d_in[2];
    const float* W1 = (const float*)d_in[3];
    const float* b1 = (const float*)d_in[4];
    const float* W2 = (const float*)d_in[5];
    const float* b2 = (const float*)d_in[6];
    const float* fw = (const float*)d_in[7];
    float* out = (float*)d_out;
    long osz = (long)out_size;

    cudaFuncSetAttribute(k_gemm1, cudaFuncAttributeMaxDynamicSharedMemorySize, SMEM_BYTES);
    cudaFuncSetAttribute(k_gemm2, cudaFuncAttributeMaxDynamicSharedMemorySize, SMEM_BYTES);

    k_init<<<1, 32>>>();
    k_router<<<NTOK / 8, 256>>>(x, rW, rb, out, osz);
    k_aux<<<1, 1>>>(out, osz);
    k_split_x<<<(NTOK * DDIM / 4) / 256, 256>>>((const float4*)x);
    k_split_tr<<<dim3(HDIM / 32, DDIM / 32, NEXP), dim3(32, 8)>>>(W1, DDIM, HDIM, 0);
    k_split_tr<<<dim3(DDIM / 32, HDIM / 32, NEXP), dim3(32, 8)>>>(W2, HDIM, DDIM, 1);
    k_gemm1<<<dim3(32, 16, 8), 256, SMEM_BYTES>>>(b1);
    k_gemm2<<<dim3(32, 4, 8), 256, SMEM_BYTES>>>(b2, fw);
    k_combine<<<NTOK, 128>>>(out);
}

// round 4
// speedup vs baseline: 2.4050x; 1.0668x over previous
#include <cuda_runtime.h>
#include <cuda_bf16.h>
#include <math.h>
#include <cstdint>

#define NTOK 4096
#define DDIM 512
#define HDIM 2048
#define NEXP 8
#define NC 7
#define BETA_FIXED (1.0f/3.0f)
#define BETA_DYN   (2.0f/3.0f)

// ================= scratch (static device globals) =================
__device__ __nv_bfloat16 g_xh[NTOK * DDIM];
__device__ __nv_bfloat16 g_xl[NTOK * DDIM];
__device__ __nv_bfloat16 g_w1h[NEXP * HDIM * DDIM];   // [E][H][D]  (K-major gemm1 B)
__device__ __nv_bfloat16 g_w1l[NEXP * HDIM * DDIM];
__device__ __nv_bfloat16 g_w2h[NEXP * DDIM * HDIM];   // [E][D][H]  (K-major gemm2 B)
__device__ __nv_bfloat16 g_w2l[NEXP * DDIM * HDIM];
__device__ __nv_bfloat16 g_hh[(size_t)NEXP * NTOK * HDIM];  // hidden split-bf16 hi
__device__ __nv_bfloat16 g_hl[(size_t)NEXP * NTOK * HDIM];  // hidden split-bf16 lo
__device__ float g_Y[(size_t)NEXP * NTOK * DDIM];
__device__ int   g_list[NEXP * NTOK];
__device__ float g_scale[NEXP * NTOK];
__device__ int   g_pos[NTOK * 2];
__device__ int   g_cnt[NEXP];
__device__ float g_imp[NC];

// ================= helpers =================
__device__ __forceinline__ uint32_t smem_u32(const void* p) {
    uint32_t a;
    asm("{ .reg .u64 t; cvta.to.shared.u64 t, %1; cvt.u32.u64 %0, t; }" : "=r"(a) : "l"(p));
    return a;
}
__device__ __forceinline__ void cpa16(uint32_t dst, const void* src) {
    asm volatile("cp.async.cg.shared.global [%0], [%1], 16;" :: "r"(dst), "l"(src));
}
#define CPA_COMMIT() asm volatile("cp.async.commit_group;" ::: "memory")
#define CPA_WAIT0()  asm volatile("cp.async.wait_group 0;" ::: "memory")

__device__ __forceinline__ void ldm_x4(uint32_t addr, uint32_t* r) {
    asm volatile("ldmatrix.sync.aligned.m8n8.x4.shared.b16 {%0,%1,%2,%3}, [%4];"
        : "=r"(r[0]), "=r"(r[1]), "=r"(r[2]), "=r"(r[3]) : "r"(addr));
}
__device__ __forceinline__ void mma16816(float* c, const uint32_t* a, uint32_t b0, uint32_t b1) {
    asm volatile("mma.sync.aligned.m16n8k16.row.col.f32.bf16.bf16.f32 "
        "{%0,%1,%2,%3}, {%4,%5,%6,%7}, {%8,%9}, {%0,%1,%2,%3};"
        : "+f"(c[0]), "+f"(c[1]), "+f"(c[2]), "+f"(c[3])
        : "r"(a[0]), "r"(a[1]), "r"(a[2]), "r"(a[3]), "r"(b0), "r"(b1));
}
__device__ __forceinline__ void split2(float v, __nv_bfloat16& h, __nv_bfloat16& l) {
    h = __float2bfloat16(v);
    l = __float2bfloat16(v - __bfloat162float(h));
}
__device__ __forceinline__ uint32_t pack2(__nv_bfloat16 a, __nv_bfloat16 b) {
    return ((uint32_t)__bfloat16_as_ushort(b) << 16) | __bfloat16_as_ushort(a);
}

// smem tile layout (per stage): Ah | Al | Bh | Bl, each 128 rows x 80B (32 bf16 data + 16B pad)
#define RSB 80
#define HALF_BYTES (128 * RSB)        // 10240
#define OFF_AH 0
#define OFF_AL (1 * HALF_BYTES)
#define OFF_BH (2 * HALF_BYTES)
#define OFF_BL (3 * HALF_BYTES)
#define STAGE_BYTES (4 * HALF_BYTES)  // 40960
#define SM_TILES 1024                 // aux region first
#define SMEM_BYTES (SM_TILES + 2 * STAGE_BYTES)   // 82944  -> 2 CTAs/SM

// ================= init =================
__global__ void k_init() {
    int t = threadIdx.x;
    if (t < NEXP) g_cnt[t] = 0;
    if (t < NC)   g_imp[t] = 0.f;
}

// ================= router =================
__global__ void k_router(const float* __restrict__ x,
                         const float* __restrict__ rW,
                         const float* __restrict__ rb,
                         float* __restrict__ out, long out_size) {
    __shared__ float imp_s[NC];
    int t = threadIdx.x;
    if (t < NC) imp_s[t] = 0.f;
    __syncthreads();

    int w = t >> 5, lane = t & 31;
    int n = blockIdx.x * 8 + w;

    float acc[NC];
#pragma unroll
    for (int j = 0; j < NC; j++) acc[j] = 0.f;

    const float* xr = x + (size_t)n * DDIM;
    for (int k = lane; k < DDIM; k += 32) {
        float xv = xr[k];
        const float* wr = rW + (size_t)k * NC;
#pragma unroll
        for (int j = 0; j < NC; j++) acc[j] += xv * wr[j];
    }
#pragma unroll
    for (int j = 0; j < NC; j++) {
#pragma unroll
        for (int off = 16; off > 0; off >>= 1)
            acc[j] += __shfl_xor_sync(0xffffffffu, acc[j], off);
        acc[j] += rb[j];
    }

    if (lane == 0) {
        float m = acc[0];
#pragma unroll
        for (int j = 1; j < NC; j++) m = fmaxf(m, acc[j]);
        float p[NC], s = 0.f;
#pragma unroll
        for (int j = 0; j < NC; j++) { p[j] = __expf(acc[j] - m); s += p[j]; }
        float inv = 1.f / s;
#pragma unroll
        for (int j = 0; j < NC; j++) atomicAdd(&imp_s[j], p[j] * inv);

        int i1 = 0;
#pragma unroll
        for (int j = 1; j < NC; j++) if (acc[j] > acc[i1]) i1 = j;
        int i2 = (i1 == 0) ? 1 : 0;
#pragma unroll
        for (int j = 0; j < NC; j++) if (j != i1 && acc[j] > acc[i2]) i2 = j;

        float e2 = __expf(acc[i2] - acc[i1]);
        float den = 1.f / (1.f + e2);
        float gA = den, gB = e2 * den;

        int eA = i1 + 1, eB = i2 + 1;
        int rA = atomicAdd(&g_cnt[eA], 1);
        int rB = atomicAdd(&g_cnt[eB], 1);
        int rowA = eA * NTOK + rA;
        int rowB = eB * NTOK + rB;
        g_list[rowA] = n;  g_list[rowB] = n;
        g_scale[rowA] = BETA_DYN * gA;
        g_scale[rowB] = BETA_DYN * gB;
        g_pos[2 * n]     = rowA;
        g_pos[2 * n + 1] = rowB;

        long selbase = (long)NTOK * DDIM + 2;
        if (selbase + 2 * (long)NTOK <= out_size) {
            out[selbase + 2 * n]     = (float)eA;
            out[selbase + 2 * n + 1] = (float)eB;
        }
    }
    __syncthreads();
    if (t < NC) atomicAdd(&g_imp[t], imp_s[t]);
}

__global__ void k_aux(float* __restrict__ out, long out_size) {
    float lbl = 0.f, ent = 0.f;
#pragma unroll
    for (int j = 0; j < NC; j++) {
        float imp = g_imp[j] / (float)NTOK;
        float d = imp - (1.0f / NC);
        lbl += d * d;
        ent -= imp * logf(fmaxf(imp, 1e-8f));
    }
    lbl *= (1.0f / NC);
    long base = (long)NTOK * DDIM;
    if (base < out_size)     out[base]     = lbl;
    if (base + 1 < out_size) out[base + 1] = ent;
}

// ================= split/transpose conversions =================
__global__ void k_split_x(const float4* __restrict__ x) {
    int i = blockIdx.x * blockDim.x + threadIdx.x;
    float4 v = x[i];
    __nv_bfloat16 h0, h1, h2, h3, l0, l1, l2, l3;
    split2(v.x, h0, l0); split2(v.y, h1, l1);
    split2(v.z, h2, l2); split2(v.w, h3, l3);
    uint2 hh, ll;
    hh.x = pack2(h0, h1); hh.y = pack2(h2, h3);
    ll.x = pack2(l0, l1); ll.y = pack2(l2, l3);
    ((uint2*)g_xh)[i] = hh;
    ((uint2*)g_xl)[i] = ll;
}

// in [E][R][C] f32 -> out [E][C][R] bf16 hi/lo; which: 0=W1, 1=W2
__global__ void k_split_tr(const float* __restrict__ in, int R, int C, int which) {
    __shared__ float tile[32][33];
    int e = blockIdx.z;
    int c0 = blockIdx.x * 32, r0 = blockIdx.y * 32;
    int tx = threadIdx.x, ty = threadIdx.y;   // 32 x 8
    const float* ip = in + (size_t)e * R * C;
#pragma unroll
    for (int i = 0; i < 4; i++)
        tile[ty + 8 * i][tx] = ip[(size_t)(r0 + ty + 8 * i) * C + c0 + tx];
    __syncthreads();
    __nv_bfloat16* oh = which ? g_w2h : g_w1h;
    __nv_bfloat16* ol = which ? g_w2l : g_w1l;
#pragma unroll
    for (int i = 0; i < 4; i++) {
        float v = tile[tx][ty + 8 * i];
        __nv_bfloat16 h, l;
        split2(v, h, l);
        size_t o = ((size_t)e * C + c0 + ty + 8 * i) * R + r0 + tx;
        oh[o] = h; ol[o] = l;
    }
}

// ================= shared GEMM compute core =================
// block 128x128, 8 warps (2Mx4N), warp tile 64x32, k-chunk 32 (2 x k16)
__device__ __forceinline__ void gemm_compute_chunk(
    uint32_t tb, int wm, int wn, int lane, float acc[4][4][4])
{
    uint32_t a_row = (uint32_t)((lane & 7) + ((lane >> 3) & 1) * 8);
    uint32_t a_kh  = (uint32_t)(lane >> 4);
    uint32_t a_base_h = tb + OFF_AH + (wm * 64 + a_row) * RSB + a_kh * 16;
    uint32_t a_base_l = tb + OFF_AL + (wm * 64 + a_row) * RSB + a_kh * 16;
    uint32_t b_base_h = tb + OFF_BH + (wn * 32 + lane) * RSB;
    uint32_t b_base_l = tb + OFF_BL + (wn * 32 + lane) * RSB;

#pragma unroll
    for (int kk = 0; kk < 2; kk++) {
        uint32_t ah[4][4], al[4][4];
#pragma unroll
        for (int mf = 0; mf < 4; mf++) {
            ldm_x4(a_base_h + mf * 16 * RSB + kk * 32, ah[mf]);
            ldm_x4(a_base_l + mf * 16 * RSB + kk * 32, al[mf]);
        }
        uint32_t bh0[4], bh1[4], bl0[4], bl1[4];
        ldm_x4(b_base_h + kk * 32,      bh0);
        ldm_x4(b_base_h + kk * 32 + 16, bh1);
        ldm_x4(b_base_l + kk * 32,      bl0);
        ldm_x4(b_base_l + kk * 32 + 16, bl1);

#pragma unroll
        for (int mi = 0; mi < 4; mi++)
#pragma unroll
            for (int ni = 0; ni < 4; ni++)
                mma16816(acc[mi][ni], ah[mi], bh0[ni], bh1[ni]);
#pragma unroll
        for (int mi = 0; mi < 4; mi++)
#pragma unroll
            for (int ni = 0; ni < 4; ni++)
                mma16816(acc[mi][ni], ah[mi], bl0[ni], bl1[ni]);
#pragma unroll
        for (int mi = 0; mi < 4; mi++)
#pragma unroll
            for (int ni = 0; ni < 4; ni++)
                mma16816(acc[mi][ni], al[mi], bh0[ni], bh1[ni]);
    }
}

// ================= GEMM 1: H = relu(Xg @ W1t[e] + b1[e]) -> split bf16 =================
__global__ void __launch_bounds__(256, 2) k_gemm1(const float* __restrict__ b1) {
    int s = blockIdx.z;
    int cnt = (s == 0) ? NTOK : g_cnt[s];
    int m0 = blockIdx.x * 128;
    if (m0 >= cnt) return;
    int n0 = blockIdx.y * 128;

    extern __shared__ char smem[];
    uint32_t sb = smem_u32(smem);
    int t = threadIdx.x;
    int wid = t >> 5, lane = t & 31;
    int wm = wid >> 2, wn = wid & 3;
    int* toks = (int*)smem;

    if (t < 128) {
        int m = m0 + t;
        toks[t] = (m < cnt) ? ((s == 0) ? m : g_list[s * NTOK + m]) : 0;
    }
    __syncthreads();

    auto load_chunk = [&](int st, int k0) {
        uint32_t base = sb + SM_TILES + st * STAGE_BYTES;
#pragma unroll
        for (int i = 0; i < 2; i++) {
            int id = i * 256 + t;          // 0..511
            int row = id >> 2, seg = id & 3;
            uint32_t d = base + row * RSB + seg * 16;
            size_t aoff = (size_t)toks[row] * DDIM + k0 + seg * 8;
            cpa16(d + OFF_AH, g_xh + aoff);
            cpa16(d + OFF_AL, g_xl + aoff);
            size_t boff = ((size_t)s * HDIM + n0 + row) * DDIM + k0 + seg * 8;
            cpa16(d + OFF_BH, g_w1h + boff);
            cpa16(d + OFF_BL, g_w1l + boff);
        }
        CPA_COMMIT();
    };

    float acc[4][4][4];
#pragma unroll
    for (int mi = 0; mi < 4; mi++)
#pragma unroll
        for (int ni = 0; ni < 4; ni++)
#pragma unroll
            for (int q = 0; q < 4; q++) acc[mi][ni][q] = 0.f;

    load_chunk(0, 0);
    const int CH = DDIM / 32;   // 16
    for (int c = 0; c < CH; c++) {
        CPA_WAIT0();
        __syncthreads();
        if (c + 1 < CH) load_chunk((c + 1) & 1, (c + 1) * 32);
        gemm_compute_chunk(sb + SM_TILES + (c & 1) * STAGE_BYTES, wm, wn, lane, acc);
    }

    // epilogue: bias + relu + split-bf16 store
    const float* bp = b1 + (size_t)s * HDIM;
#pragma unroll
    for (int mi = 0; mi < 4; mi++) {
        int mA = m0 + wm * 64 + mi * 16 + (lane >> 2);
        int mB = mA + 8;
        size_t rA = ((size_t)s * NTOK + mA) * HDIM;
        size_t rB = ((size_t)s * NTOK + mB) * HDIM;
        bool vA = mA < cnt, vB = mB < cnt;
#pragma unroll
        for (int ni = 0; ni < 4; ni++) {
            int col = n0 + wn * 32 + ni * 8 + 2 * (lane & 3);
            float bc0 = __ldg(bp + col), bc1 = __ldg(bp + col + 1);
            if (vA) {
                float v0 = fmaxf(acc[mi][ni][0] + bc0, 0.f);
                float v1 = fmaxf(acc[mi][ni][1] + bc1, 0.f);
                __nv_bfloat16 h0, h1, l0, l1;
                split2(v0, h0, l0); split2(v1, h1, l1);
                *(uint32_t*)(g_hh + rA + col) = pack2(h0, h1);
                *(uint32_t*)(g_hl + rA + col) = pack2(l0, l1);
            }
            if (vB) {
                float v0 = fmaxf(acc[mi][ni][2] + bc0, 0.f);
                float v1 = fmaxf(acc[mi][ni][3] + bc1, 0.f);
                __nv_bfloat16 h0, h1, l0, l1;
                split2(v0, h0, l0); split2(v1, h1, l1);
                *(uint32_t*)(g_hh + rB + col) = pack2(h0, h1);
                *(uint32_t*)(g_hl + rB + col) = pack2(l0, l1);
            }
        }
    }
}

// ================= GEMM 2: Y = scale * (H @ W2t[e] + b2[e]) =================
__global__ void __launch_bounds__(256, 2) k_gemm2(const float* __restrict__ b2,
                                                  const float* __restrict__ fw) {
    int s = blockIdx.z;
    int cnt = (s == 0) ? NTOK : g_cnt[s];
    int m0 = blockIdx.x * 128;
    if (m0 >= cnt) return;
    int n0 = blockIdx.y * 128;

    extern __shared__ char smem[];
    uint32_t sb = smem_u32(smem);
    int t = threadIdx.x;
    int wid = t >> 5, lane = t & 31;
    int wm = wid >> 2, wn = wid & 3;
    float* scl = (float*)smem;

    if (t < 128) {
        int m = m0 + t;
        scl[t] = (m < cnt) ? ((s == 0) ? BETA_FIXED * fw[0] : g_scale[s * NTOK + m]) : 0.f;
    }
    __syncthreads();

    auto load_chunk = [&](int st, int k0) {
        uint32_t base = sb + SM_TILES + st * STAGE_BYTES;
#pragma unroll
        for (int i = 0; i < 2; i++) {
            int id = i * 256 + t;
            int row = id >> 2, seg = id & 3;
            uint32_t d = base + row * RSB + seg * 16;
            size_t aoff = ((size_t)s * NTOK + m0 + row) * HDIM + k0 + seg * 8;
            cpa16(d + OFF_AH, g_hh + aoff);
            cpa16(d + OFF_AL, g_hl + aoff);
            size_t boff = ((size_t)s * DDIM + n0 + row) * HDIM + k0 + seg * 8;
            cpa16(d + OFF_BH, g_w2h + boff);
            cpa16(d + OFF_BL, g_w2l + boff);
        }
        CPA_COMMIT();
    };

    float acc[4][4][4];
#pragma unroll
    for (int mi = 0; mi < 4; mi++)
#pragma unroll
        for (int ni = 0; ni < 4; ni++)
#pragma unroll
            for (int q = 0; q < 4; q++) acc[mi][ni][q] = 0.f;

    load_chunk(0, 0);
    const int CH = HDIM / 32;   // 64
    for (int c = 0; c < CH; c++) {
        CPA_WAIT0();
        __syncthreads();
        if (c + 1 < CH) load_chunk((c + 1) & 1, (c + 1) * 32);
        gemm_compute_chunk(sb + SM_TILES + (c & 1) * STAGE_BYTES, wm, wn, lane, acc);
    }

    // epilogue: (acc + bias) * scale, fp32 store
    const float* bp = b2 + (size_t)s * DDIM;
#pragma unroll
    for (int mi = 0; mi < 4; mi++) {
        int mloc = wm * 64 + mi * 16 + (lane >> 2);
        int mA = m0 + mloc, mB = mA + 8;
        float scA = scl[mloc], scB = scl[mloc + 8];
        size_t rA = ((size_t)s * NTOK + mA) * DDIM;
        size_t rB = ((size_t)s * NTOK + mB) * DDIM;
        bool vA = mA < cnt, vB = mB < cnt;
#pragma unroll
        for (int ni = 0; ni < 4; ni++) {
            int col = n0 + wn * 32 + ni * 8 + 2 * (lane & 3);
            float bc0 = __ldg(bp + col), bc1 = __ldg(bp + col + 1);
            if (vA) {
                float2 v;
                v.x = (acc[mi][ni][0] + bc0) * scA;
                v.y = (acc[mi][ni][1] + bc1) * scA;
                *(float2*)(g_Y + rA + col) = v;
            }
            if (vB) {
                float2 v;
                v.x = (acc[mi][ni][2] + bc0) * scB;
                v.y = (acc[mi][ni][3] + bc1) * scB;
                *(float2*)(g_Y + rB + col) = v;
            }
        }
    }
}

// ================= combine =================
__global__ void k_combine(float* __restrict__ out) {
    int n = blockIdx.x;
    int t = threadIdx.x;
    const float4* y0 = (const float4*)(g_Y + (size_t)n * DDIM);
    int pA = g_pos[2 * n], pB = g_pos[2 * n + 1];
    const float4* yA = (const float4*)(g_Y + (size_t)pA * DDIM);
    const float4* yB = (const float4*)(g_Y + (size_t)pB * DDIM);
    float4 a = y0[t], b = yA[t], c = yB[t];
    float4 r;
    r.x = a.x + b.x + c.x;
    r.y = a.y + b.y + c.y;
    r.z = a.z + b.z + c.z;
    r.w = a.w + b.w + c.w;
    ((float4*)(out + (size_t)n * DDIM))[t] = r;
}

// ================= launch =================
extern "C" void kernel_launch(void* const* d_in, const int* in_sizes, int n_in,
                              void* d_out, int out_size) {
    const float* x  = (const float*)d_in[0];
    const float* rW = (const float*)d_in[1];
    const float* rb = (const float*)d_in[2];
    const float* W1 = (const float*)d_in[3];
    const float* b1 = (const float*)d_in[4];
    const float* W2 = (const float*)d_in[5];
    const float* b2 = (const float*)d_in[6];
    const float* fw = (const float*)d_in[7];
    float* out = (float*)d_out;
    long osz = (long)out_size;

    cudaFuncSetAttribute(k_gemm1, cudaFuncAttributeMaxDynamicSharedMemorySize, SMEM_BYTES);
    cudaFuncSetAttribute(k_gemm2, cudaFuncAttributeMaxDynamicSharedMemorySize, SMEM_BYTES);

    k_init<<<1, 32>>>();
    k_router<<<NTOK / 8, 256>>>(x, rW, rb, out, osz);
    k_aux<<<1, 1>>>(out, osz);
    k_split_x<<<(NTOK * DDIM / 4) / 256, 256>>>((const float4*)x);
    k_split_tr<<<dim3(HDIM / 32, DDIM / 32, NEXP), dim3(32, 8)>>>(W1, DDIM, HDIM, 0);
    k_split_tr<<<dim3(DDIM / 32, HDIM / 32, NEXP), dim3(32, 8)>>>(W2, HDIM, DDIM, 1);
    k_gemm1<<<dim3(32, 16, 8), 256, SMEM_BYTES>>>(b1);
    k_gemm2<<<dim3(32, 4, 8), 256, SMEM_BYTES>>>(b2, fw);
    k_combine<<<NTOK, 128>>>(out);
}

// round 5
// speedup vs baseline: 3.4931x; 1.4524x over previous
#include <cuda_runtime.h>
#include <cuda_fp16.h>
#include <math.h>
#include <cstdint>

#define NTOK 4096
#define DDIM 512
#define HDIM 2048
#define NEXP 8
#define NC 7
#define BETA_FIXED (1.0f/3.0f)
#define BETA_DYN   (2.0f/3.0f)

// ================= scratch (static device globals) =================
__device__ __half g_xa[NTOK * DDIM];                 // activations, single fp16
__device__ __half g_w1h[NEXP * HDIM * DDIM];         // [E][H][D] K-major, hi
__device__ __half g_w1l[NEXP * HDIM * DDIM];         // lo
__device__ __half g_w2h[NEXP * DDIM * HDIM];         // [E][D][H] K-major, hi
__device__ __half g_w2l[NEXP * DDIM * HDIM];         // lo
__device__ __half g_ha[(size_t)NEXP * NTOK * HDIM];  // hidden, single fp16
__device__ float g_Y[(size_t)NEXP * NTOK * DDIM];
__device__ int   g_list[NEXP * NTOK];
__device__ float g_scale[NEXP * NTOK];
__device__ int   g_pos[NTOK * 2];
__device__ int   g_cnt[NEXP];
__device__ float g_imp[NC];

// ================= helpers =================
__device__ __forceinline__ uint32_t smem_u32(const void* p) {
    uint32_t a;
    asm("{ .reg .u64 t; cvta.to.shared.u64 t, %1; cvt.u32.u64 %0, t; }" : "=r"(a) : "l"(p));
    return a;
}
__device__ __forceinline__ void cpa16(uint32_t dst, const void* src) {
    asm volatile("cp.async.cg.shared.global [%0], [%1], 16;" :: "r"(dst), "l"(src));
}
#define CPA_COMMIT() asm volatile("cp.async.commit_group;" ::: "memory")
#define CPA_WAIT0()  asm volatile("cp.async.wait_group 0;" ::: "memory")

__device__ __forceinline__ void ldm_x4(uint32_t addr, uint32_t* r) {
    asm volatile("ldmatrix.sync.aligned.m8n8.x4.shared.b16 {%0,%1,%2,%3}, [%4];"
        : "=r"(r[0]), "=r"(r[1]), "=r"(r[2]), "=r"(r[3]) : "r"(addr));
}
__device__ __forceinline__ void mma16816(float* c, const uint32_t* a, uint32_t b0, uint32_t b1) {
    asm volatile("mma.sync.aligned.m16n8k16.row.col.f32.f16.f16.f32 "
        "{%0,%1,%2,%3}, {%4,%5,%6,%7}, {%8,%9}, {%0,%1,%2,%3};"
        : "+f"(c[0]), "+f"(c[1]), "+f"(c[2]), "+f"(c[3])
        : "r"(a[0]), "r"(a[1]), "r"(a[2]), "r"(a[3]), "r"(b0), "r"(b1));
}
__device__ __forceinline__ void splitH(float v, __half& h, __half& l) {
    h = __float2half(v);
    l = __float2half(v - __half2float(h));
}
__device__ __forceinline__ uint32_t pack2h(__half a, __half b) {
    return ((uint32_t)__half_as_ushort(b) << 16) | __half_as_ushort(a);
}

// smem per stage: A | Bh | Bl, each 128 rows x 80B (64B data = 32 fp16, +16B pad)
#define RSB 80
#define HALF_BYTES (128 * RSB)        // 10240
#define OFF_A  0
#define OFF_BH (1 * HALF_BYTES)
#define OFF_BL (2 * HALF_BYTES)
#define STAGE_BYTES (3 * HALF_BYTES)  // 30720
#define SM_TILES 1024
#define SMEM_BYTES (SM_TILES + 2 * STAGE_BYTES)   // 62464 -> 2 CTAs/SM

// ================= init =================
__global__ void k_init() {
    int t = threadIdx.x;
    if (t < NEXP) g_cnt[t] = 0;
    if (t < NC)   g_imp[t] = 0.f;
}

// ================= router =================
__global__ void k_router(const float* __restrict__ x,
                         const float* __restrict__ rW,
                         const float* __restrict__ rb,
                         float* __restrict__ out, long out_size) {
    __shared__ float imp_s[NC];
    int t = threadIdx.x;
    if (t < NC) imp_s[t] = 0.f;
    __syncthreads();

    int w = t >> 5, lane = t & 31;
    int n = blockIdx.x * 8 + w;

    float acc[NC];
#pragma unroll
    for (int j = 0; j < NC; j++) acc[j] = 0.f;

    const float* xr = x + (size_t)n * DDIM;
    for (int k = lane; k < DDIM; k += 32) {
        float xv = xr[k];
        const float* wr = rW + (size_t)k * NC;
#pragma unroll
        for (int j = 0; j < NC; j++) acc[j] += xv * wr[j];
    }
#pragma unroll
    for (int j = 0; j < NC; j++) {
#pragma unroll
        for (int off = 16; off > 0; off >>= 1)
            acc[j] += __shfl_xor_sync(0xffffffffu, acc[j], off);
        acc[j] += rb[j];
    }

    if (lane == 0) {
        float m = acc[0];
#pragma unroll
        for (int j = 1; j < NC; j++) m = fmaxf(m, acc[j]);
        float p[NC], s = 0.f;
#pragma unroll
        for (int j = 0; j < NC; j++) { p[j] = __expf(acc[j] - m); s += p[j]; }
        float inv = 1.f / s;
#pragma unroll
        for (int j = 0; j < NC; j++) atomicAdd(&imp_s[j], p[j] * inv);

        int i1 = 0;
#pragma unroll
        for (int j = 1; j < NC; j++) if (acc[j] > acc[i1]) i1 = j;
        int i2 = (i1 == 0) ? 1 : 0;
#pragma unroll
        for (int j = 0; j < NC; j++) if (j != i1 && acc[j] > acc[i2]) i2 = j;

        float e2 = __expf(acc[i2] - acc[i1]);
        float den = 1.f / (1.f + e2);
        float gA = den, gB = e2 * den;

        int eA = i1 + 1, eB = i2 + 1;
        int rA = atomicAdd(&g_cnt[eA], 1);
        int rB = atomicAdd(&g_cnt[eB], 1);
        int rowA = eA * NTOK + rA;
        int rowB = eB * NTOK + rB;
        g_list[rowA] = n;  g_list[rowB] = n;
        g_scale[rowA] = BETA_DYN * gA;
        g_scale[rowB] = BETA_DYN * gB;
        g_pos[2 * n]     = rowA;
        g_pos[2 * n + 1] = rowB;

        long selbase = (long)NTOK * DDIM + 2;
        if (selbase + 2 * (long)NTOK <= out_size) {
            out[selbase + 2 * n]     = (float)eA;
            out[selbase + 2 * n + 1] = (float)eB;
        }
    }
    __syncthreads();
    if (t < NC) atomicAdd(&g_imp[t], imp_s[t]);
}

__global__ void k_aux(float* __restrict__ out, long out_size) {
    float lbl = 0.f, ent = 0.f;
#pragma unroll
    for (int j = 0; j < NC; j++) {
        float imp = g_imp[j] / (float)NTOK;
        float d = imp - (1.0f / NC);
        lbl += d * d;
        ent -= imp * logf(fmaxf(imp, 1e-8f));
    }
    lbl *= (1.0f / NC);
    long base = (long)NTOK * DDIM;
    if (base < out_size)     out[base]     = lbl;
    if (base + 1 < out_size) out[base + 1] = ent;
}

// ================= conversions =================
__global__ void k_cvt_x(const float4* __restrict__ x) {
    int i = blockIdx.x * blockDim.x + threadIdx.x;
    float4 v = x[i];
    uint2 p;
    p.x = pack2h(__float2half(v.x), __float2half(v.y));
    p.y = pack2h(__float2half(v.z), __float2half(v.w));
    ((uint2*)g_xa)[i] = p;
}

// in [E][R][C] f32 -> out [E][C][R] fp16 hi/lo; which: 0=W1, 1=W2
__global__ void k_split_tr(const float* __restrict__ in, int R, int C, int which) {
    __shared__ float tile[32][33];
    int e = blockIdx.z;
    int c0 = blockIdx.x * 32, r0 = blockIdx.y * 32;
    int tx = threadIdx.x, ty = threadIdx.y;   // 32 x 8
    const float* ip = in + (size_t)e * R * C;
#pragma unroll
    for (int i = 0; i < 4; i++)
        tile[ty + 8 * i][tx] = ip[(size_t)(r0 + ty + 8 * i) * C + c0 + tx];
    __syncthreads();
    __half* oh = which ? g_w2h : g_w1h;
    __half* ol = which ? g_w2l : g_w1l;
#pragma unroll
    for (int i = 0; i < 4; i++) {
        float v = tile[tx][ty + 8 * i];
        __half h, l;
        splitH(v, h, l);
        size_t o = ((size_t)e * C + c0 + ty + 8 * i) * R + r0 + tx;
        oh[o] = h; ol[o] = l;
    }
}

// ================= shared GEMM compute core =================
// block 128x128, 8 warps (2Mx4N), warp tile 64x32, k-chunk 32 (2 x k16), 2 passes
__device__ __forceinline__ void gemm_compute_chunk(
    uint32_t tb, int wm, int wn, int lane, float acc[4][4][4])
{
    uint32_t a_row = (uint32_t)((lane & 7) + ((lane >> 3) & 1) * 8);
    uint32_t a_kh  = (uint32_t)(lane >> 4);
    uint32_t a_base = tb + OFF_A + (wm * 64 + a_row) * RSB + a_kh * 16;
    uint32_t b_base_h = tb + OFF_BH + (wn * 32 + lane) * RSB;
    uint32_t b_base_l = tb + OFF_BL + (wn * 32 + lane) * RSB;

#pragma unroll
    for (int kk = 0; kk < 2; kk++) {
        uint32_t ah[4][4];
#pragma unroll
        for (int mf = 0; mf < 4; mf++)
            ldm_x4(a_base + mf * 16 * RSB + kk * 32, ah[mf]);
        uint32_t bh0[4], bh1[4], bl0[4], bl1[4];
        ldm_x4(b_base_h + kk * 32,      bh0);
        ldm_x4(b_base_h + kk * 32 + 16, bh1);
        ldm_x4(b_base_l + kk * 32,      bl0);
        ldm_x4(b_base_l + kk * 32 + 16, bl1);

#pragma unroll
        for (int mi = 0; mi < 4; mi++)
#pragma unroll
            for (int ni = 0; ni < 4; ni++)
                mma16816(acc[mi][ni], ah[mi], bh0[ni], bh1[ni]);
#pragma unroll
        for (int mi = 0; mi < 4; mi++)
#pragma unroll
            for (int ni = 0; ni < 4; ni++)
                mma16816(acc[mi][ni], ah[mi], bl0[ni], bl1[ni]);
    }
}

// ================= GEMM 1: H = relu(Xg @ W1t[e] + b1[e]) -> fp16 =================
__global__ void __launch_bounds__(256, 2) k_gemm1(const float* __restrict__ b1) {
    int s = blockIdx.z;
    int cnt = (s == 0) ? NTOK : g_cnt[s];
    int m0 = blockIdx.x * 128;
    if (m0 >= cnt) return;
    int n0 = blockIdx.y * 128;

    extern __shared__ char smem[];
    uint32_t sb = smem_u32(smem);
    int t = threadIdx.x;
    int wid = t >> 5, lane = t & 31;
    int wm = wid >> 2, wn = wid & 3;
    int* toks = (int*)smem;

    if (t < 128) {
        int m = m0 + t;
        toks[t] = (m < cnt) ? ((s == 0) ? m : g_list[s * NTOK + m]) : 0;
    }
    __syncthreads();

    auto load_chunk = [&](int st, int k0) {
        uint32_t base = sb + SM_TILES + st * STAGE_BYTES;
#pragma unroll
        for (int i = 0; i < 2; i++) {
            int id = i * 256 + t;          // 0..511
            int row = id >> 2, seg = id & 3;
            uint32_t d = base + row * RSB + seg * 16;
            size_t aoff = (size_t)toks[row] * DDIM + k0 + seg * 8;
            cpa16(d + OFF_A, g_xa + aoff);
            size_t boff = ((size_t)s * HDIM + n0 + row) * DDIM + k0 + seg * 8;
            cpa16(d + OFF_BH, g_w1h + boff);
            cpa16(d + OFF_BL, g_w1l + boff);
        }
        CPA_COMMIT();
    };

    float acc[4][4][4];
#pragma unroll
    for (int mi = 0; mi < 4; mi++)
#pragma unroll
        for (int ni = 0; ni < 4; ni++)
#pragma unroll
            for (int q = 0; q < 4; q++) acc[mi][ni][q] = 0.f;

    load_chunk(0, 0);
    const int CH = DDIM / 32;   // 16
    for (int c = 0; c < CH; c++) {
        CPA_WAIT0();
        __syncthreads();
        if (c + 1 < CH) load_chunk((c + 1) & 1, (c + 1) * 32);
        gemm_compute_chunk(sb + SM_TILES + (c & 1) * STAGE_BYTES, wm, wn, lane, acc);
    }

    // epilogue: bias + relu -> single fp16
    const float* bp = b1 + (size_t)s * HDIM;
#pragma unroll
    for (int mi = 0; mi < 4; mi++) {
        int mA = m0 + wm * 64 + mi * 16 + (lane >> 2);
        int mB = mA + 8;
        size_t rA = ((size_t)s * NTOK + mA) * HDIM;
        size_t rB = ((size_t)s * NTOK + mB) * HDIM;
        bool vA = mA < cnt, vB = mB < cnt;
#pragma unroll
        for (int ni = 0; ni < 4; ni++) {
            int col = n0 + wn * 32 + ni * 8 + 2 * (lane & 3);
            float bc0 = __ldg(bp + col), bc1 = __ldg(bp + col + 1);
            if (vA) {
                float v0 = fmaxf(acc[mi][ni][0] + bc0, 0.f);
                float v1 = fmaxf(acc[mi][ni][1] + bc1, 0.f);
                *(uint32_t*)(g_ha + rA + col) = pack2h(__float2half(v0), __float2half(v1));
            }
            if (vB) {
                float v0 = fmaxf(acc[mi][ni][2] + bc0, 0.f);
                float v1 = fmaxf(acc[mi][ni][3] + bc1, 0.f);
                *(uint32_t*)(g_ha + rB + col) = pack2h(__float2half(v0), __float2half(v1));
            }
        }
    }
}

// ================= GEMM 2: Y = scale * (H @ W2t[e] + b2[e]) =================
__global__ void __launch_bounds__(256, 2) k_gemm2(const float* __restrict__ b2,
                                                  const float* __restrict__ fw) {
    int s = blockIdx.z;
    int cnt = (s == 0) ? NTOK : g_cnt[s];
    int m0 = blockIdx.x * 128;
    if (m0 >= cnt) return;
    int n0 = blockIdx.y * 128;

    extern __shared__ char smem[];
    uint32_t sb = smem_u32(smem);
    int t = threadIdx.x;
    int wid = t >> 5, lane = t & 31;
    int wm = wid >> 2, wn = wid & 3;
    float* scl = (float*)smem;

    if (t < 128) {
        int m = m0 + t;
        scl[t] = (m < cnt) ? ((s == 0) ? BETA_FIXED * fw[0] : g_scale[s * NTOK + m]) : 0.f;
    }
    __syncthreads();

    auto load_chunk = [&](int st, int k0) {
        uint32_t base = sb + SM_TILES + st * STAGE_BYTES;
#pragma unroll
        for (int i = 0; i < 2; i++) {
            int id = i * 256 + t;
            int row = id >> 2, seg = id & 3;
            uint32_t d = base + row * RSB + seg * 16;
            size_t aoff = ((size_t)s * NTOK + m0 + row) * HDIM + k0 + seg * 8;
            cpa16(d + OFF_A, g_ha + aoff);
            size_t boff = ((size_t)s * DDIM + n0 + row) * HDIM + k0 + seg * 8;
            cpa16(d + OFF_BH, g_w2h + boff);
            cpa16(d + OFF_BL, g_w2l + boff);
        }
        CPA_COMMIT();
    };

    float acc[4][4][4];
#pragma unroll
    for (int mi = 0; mi < 4; mi++)
#pragma unroll
        for (int ni = 0; ni < 4; ni++)
#pragma unroll
            for (int q = 0; q < 4; q++) acc[mi][ni][q] = 0.f;

    load_chunk(0, 0);
    const int CH = HDIM / 32;   // 64
    for (int c = 0; c < CH; c++) {
        CPA_WAIT0();
        __syncthreads();
        if (c + 1 < CH) load_chunk((c + 1) & 1, (c + 1) * 32);
        gemm_compute_chunk(sb + SM_TILES + (c & 1) * STAGE_BYTES, wm, wn, lane, acc);
    }

    // epilogue: (acc + bias) * scale, fp32 store
    const float* bp = b2 + (size_t)s * DDIM;
#pragma unroll
    for (int mi = 0; mi < 4; mi++) {
        int mloc = wm * 64 + mi * 16 + (lane >> 2);
        int mA = m0 + mloc, mB = mA + 8;
        float scA = scl[mloc], scB = scl[mloc + 8];
        size_t rA = ((size_t)s * NTOK + mA) * DDIM;
        size_t rB = ((size_t)s * NTOK + mB) * DDIM;
        bool vA = mA < cnt, vB = mB < cnt;
#pragma unroll
        for (int ni = 0; ni < 4; ni++) {
            int col = n0 + wn * 32 + ni * 8 + 2 * (lane & 3);
            float bc0 = __ldg(bp + col), bc1 = __ldg(bp + col + 1);
            if (vA) {
                float2 v;
                v.x = (acc[mi][ni][0] + bc0) * scA;
                v.y = (acc[mi][ni][1] + bc1) * scA;
                *(float2*)(g_Y + rA + col) = v;
            }
            if (vB) {
                float2 v;
                v.x = (acc[mi][ni][2] + bc0) * scB;
                v.y = (acc[mi][ni][3] + bc1) * scB;
                *(float2*)(g_Y + rB + col) = v;
            }
        }
    }
}

// ================= combine =================
__global__ void k_combine(float* __restrict__ out) {
    int n = blockIdx.x;
    int t = threadIdx.x;
    const float4* y0 = (const float4*)(g_Y + (size_t)n * DDIM);
    int pA = g_pos[2 * n], pB = g_pos[2 * n + 1];
    const float4* yA = (const float4*)(g_Y + (size_t)pA * DDIM);
    const float4* yB = (const float4*)(g_Y + (size_t)pB * DDIM);
    float4 a = y0[t], b = yA[t], c = yB[t];
    float4 r;
    r.x = a.x + b.x + c.x;
    r.y = a.y + b.y + c.y;
    r.z = a.z + b.z + c.z;
    r.w = a.w + b.w + c.w;
    ((float4*)(out + (size_t)n * DDIM))[t] = r;
}

// ================= launch =================
extern "C" void kernel_launch(void* const* d_in, const int* in_sizes, int n_in,
                              void* d_out, int out_size) {
    const float* x  = (const float*)d_in[0];
    const float* rW = (const float*)d_in[1];
    const float* rb = (const float*)d_in[2];
    const float* W1 = (const float*)d_in[3];
    const float* b1 = (const float*)d_in[4];
    const float* W2 = (const float*)d_in[5];
    const float* b2 = (const float*)d_in[6];
    const float* fw = (const float*)d_in[7];
    float* out = (float*)d_out;
    long osz = (long)out_size;

    cudaFuncSetAttribute(k_gemm1, cudaFuncAttributeMaxDynamicSharedMemorySize, SMEM_BYTES);
    cudaFuncSetAttribute(k_gemm2, cudaFuncAttributeMaxDynamicSharedMemorySize, SMEM_BYTES);

    k_init<<<1, 32>>>();
    k_router<<<NTOK / 8, 256>>>(x, rW, rb, out, osz);
    k_aux<<<1, 1>>>(out, osz);
    k_cvt_x<<<(NTOK * DDIM / 4) / 256, 256>>>((const float4*)x);
    k_split_tr<<<dim3(HDIM / 32, DDIM / 32, NEXP), dim3(32, 8)>>>(W1, DDIM, HDIM, 0);
    k_split_tr<<<dim3(DDIM / 32, HDIM / 32, NEXP), dim3(32, 8)>>>(W2, HDIM, DDIM, 1);
    k_gemm1<<<dim3(32, 16, 8), 256, SMEM_BYTES>>>(b1);
    k_gemm2<<<dim3(32, 4, 8), 256, SMEM_BYTES>>>(b2, fw);
    k_combine<<<NTOK, 128>>>(out);
}

// round 6
// speedup vs baseline: 5.2978x; 1.5167x over previous
#include <cuda_runtime.h>
#include <cuda_fp16.h>
#include <math.h>
#include <cstdint>

#define NTOK 4096
#define DDIM 512
#define HDIM 2048
#define NEXP 8
#define NC 7
#define BETA_FIXED (1.0f/3.0f)
#define BETA_DYN   (2.0f/3.0f)

// ================= scratch (static device globals) =================
__device__ __half g_xa[NTOK * DDIM];                 // activations fp16
__device__ __half g_w1[NEXP * HDIM * DDIM];          // [E][H][D] K-major fp16
__device__ __half g_w2[NEXP * DDIM * HDIM];          // [E][D][H] K-major fp16
__device__ __half g_ha[(size_t)NEXP * NTOK * HDIM];  // hidden fp16
__device__ float g_Y[(size_t)NEXP * NTOK * DDIM];
__device__ int   g_list[NEXP * NTOK];
__device__ float g_scale[NEXP * NTOK];
__device__ int   g_pos[NTOK * 2];
__device__ int   g_cnt[NEXP];
__device__ float g_imp[NC];

// ================= helpers =================
__device__ __forceinline__ uint32_t smem_u32(const void* p) {
    uint32_t a;
    asm("{ .reg .u64 t; cvta.to.shared.u64 t, %1; cvt.u32.u64 %0, t; }" : "=r"(a) : "l"(p));
    return a;
}
__device__ __forceinline__ void cpa16(uint32_t dst, const void* src) {
    asm volatile("cp.async.cg.shared.global [%0], [%1], 16;" :: "r"(dst), "l"(src));
}
#define CPA_COMMIT() asm volatile("cp.async.commit_group;" ::: "memory")
#define CPA_WAIT0()  asm volatile("cp.async.wait_group 0;" ::: "memory")

__device__ __forceinline__ void ldm_x4(uint32_t addr, uint32_t* r) {
    asm volatile("ldmatrix.sync.aligned.m8n8.x4.shared.b16 {%0,%1,%2,%3}, [%4];"
        : "=r"(r[0]), "=r"(r[1]), "=r"(r[2]), "=r"(r[3]) : "r"(addr));
}
__device__ __forceinline__ void mma16816(float* c, const uint32_t* a, uint32_t b0, uint32_t b1) {
    asm volatile("mma.sync.aligned.m16n8k16.row.col.f32.f16.f16.f32 "
        "{%0,%1,%2,%3}, {%4,%5,%6,%7}, {%8,%9}, {%0,%1,%2,%3};"
        : "+f"(c[0]), "+f"(c[1]), "+f"(c[2]), "+f"(c[3])
        : "r"(a[0]), "r"(a[1]), "r"(a[2]), "r"(a[3]), "r"(b0), "r"(b1));
}
__device__ __forceinline__ uint32_t pack2h(__half a, __half b) {
    return ((uint32_t)__half_as_ushort(b) << 16) | __half_as_ushort(a);
}

// smem per stage: A | B, each 128 rows x 80B (64B data = 32 fp16, +16B pad)
#define RSB 80
#define HALF_BYTES (128 * RSB)        // 10240
#define OFF_A  0
#define OFF_B  (1 * HALF_BYTES)
#define STAGE_BYTES (2 * HALF_BYTES)  // 20480
#define SM_TILES 1024
#define SMEM_BYTES (SM_TILES + 2 * STAGE_BYTES)   // 41984 -> 2 CTAs/SM

// ================= init =================
__global__ void k_init() {
    int t = threadIdx.x;
    if (t < NEXP) g_cnt[t] = 0;
    if (t < NC)   g_imp[t] = 0.f;
}

// ================= router =================
__global__ void k_router(const float* __restrict__ x,
                         const float* __restrict__ rW,
                         const float* __restrict__ rb,
                         float* __restrict__ out, long out_size) {
    __shared__ float imp_s[NC];
    int t = threadIdx.x;
    if (t < NC) imp_s[t] = 0.f;
    __syncthreads();

    int w = t >> 5, lane = t & 31;
    int n = blockIdx.x * 8 + w;

    float acc[NC];
#pragma unroll
    for (int j = 0; j < NC; j++) acc[j] = 0.f;

    const float* xr = x + (size_t)n * DDIM;
    for (int k = lane; k < DDIM; k += 32) {
        float xv = xr[k];
        const float* wr = rW + (size_t)k * NC;
#pragma unroll
        for (int j = 0; j < NC; j++) acc[j] += xv * wr[j];
    }
#pragma unroll
    for (int j = 0; j < NC; j++) {
#pragma unroll
        for (int off = 16; off > 0; off >>= 1)
            acc[j] += __shfl_xor_sync(0xffffffffu, acc[j], off);
        acc[j] += rb[j];
    }

    if (lane == 0) {
        float m = acc[0];
#pragma unroll
        for (int j = 1; j < NC; j++) m = fmaxf(m, acc[j]);
        float p[NC], s = 0.f;
#pragma unroll
        for (int j = 0; j < NC; j++) { p[j] = __expf(acc[j] - m); s += p[j]; }
        float inv = 1.f / s;
#pragma unroll
        for (int j = 0; j < NC; j++) atomicAdd(&imp_s[j], p[j] * inv);

        int i1 = 0;
#pragma unroll
        for (int j = 1; j < NC; j++) if (acc[j] > acc[i1]) i1 = j;
        int i2 = (i1 == 0) ? 1 : 0;
#pragma unroll
        for (int j = 0; j < NC; j++) if (j != i1 && acc[j] > acc[i2]) i2 = j;

        float e2 = __expf(acc[i2] - acc[i1]);
        float den = 1.f / (1.f + e2);
        float gA = den, gB = e2 * den;

        int eA = i1 + 1, eB = i2 + 1;
        int rA = atomicAdd(&g_cnt[eA], 1);
        int rB = atomicAdd(&g_cnt[eB], 1);
        int rowA = eA * NTOK + rA;
        int rowB = eB * NTOK + rB;
        g_list[rowA] = n;  g_list[rowB] = n;
        g_scale[rowA] = BETA_DYN * gA;
        g_scale[rowB] = BETA_DYN * gB;
        g_pos[2 * n]     = rowA;
        g_pos[2 * n + 1] = rowB;

        long selbase = (long)NTOK * DDIM + 2;
        if (selbase + 2 * (long)NTOK <= out_size) {
            out[selbase + 2 * n]     = (float)eA;
            out[selbase + 2 * n + 1] = (float)eB;
        }
    }
    __syncthreads();
    if (t < NC) atomicAdd(&g_imp[t], imp_s[t]);
}

__global__ void k_aux(float* __restrict__ out, long out_size) {
    float lbl = 0.f, ent = 0.f;
#pragma unroll
    for (int j = 0; j < NC; j++) {
        float imp = g_imp[j] / (float)NTOK;
        float d = imp - (1.0f / NC);
        lbl += d * d;
        ent -= imp * logf(fmaxf(imp, 1e-8f));
    }
    lbl *= (1.0f / NC);
    long base = (long)NTOK * DDIM;
    if (base < out_size)     out[base]     = lbl;
    if (base + 1 < out_size) out[base + 1] = ent;
}

// ================= conversions =================
__global__ void k_cvt_x(const float4* __restrict__ x) {
    int i = blockIdx.x * blockDim.x + threadIdx.x;
    float4 v = x[i];
    uint2 p;
    p.x = pack2h(__float2half(v.x), __float2half(v.y));
    p.y = pack2h(__float2half(v.z), __float2half(v.w));
    ((uint2*)g_xa)[i] = p;
}

// in [E][R][C] f32 -> out [E][C][R] fp16; which: 0=W1, 1=W2
__global__ void k_cvt_tr(const float* __restrict__ in, int R, int C, int which) {
    __shared__ float tile[32][33];
    int e = blockIdx.z;
    int c0 = blockIdx.x * 32, r0 = blockIdx.y * 32;
    int tx = threadIdx.x, ty = threadIdx.y;   // 32 x 8
    const float* ip = in + (size_t)e * R * C;
#pragma unroll
    for (int i = 0; i < 4; i++)
        tile[ty + 8 * i][tx] = ip[(size_t)(r0 + ty + 8 * i) * C + c0 + tx];
    __syncthreads();
    __half* oh = which ? g_w2 : g_w1;
#pragma unroll
    for (int i = 0; i < 4; i++) {
        float v = tile[tx][ty + 8 * i];
        size_t o = ((size_t)e * C + c0 + ty + 8 * i) * R + r0 + tx;
        oh[o] = __float2half(v);
    }
}

// ================= shared GEMM compute core =================
// block 128x128, 8 warps (2Mx4N), warp tile 64x32, k-chunk 32 (2 x k16), single pass
__device__ __forceinline__ void gemm_compute_chunk(
    uint32_t tb, int wm, int wn, int lane, float acc[4][4][4])
{
    uint32_t a_row = (uint32_t)((lane & 7) + ((lane >> 3) & 1) * 8);
    uint32_t a_kh  = (uint32_t)(lane >> 4);
    uint32_t a_base = tb + OFF_A + (wm * 64 + a_row) * RSB + a_kh * 16;
    uint32_t b_base = tb + OFF_B + (wn * 32 + lane) * RSB;

#pragma unroll
    for (int kk = 0; kk < 2; kk++) {
        uint32_t ah[4][4];
#pragma unroll
        for (int mf = 0; mf < 4; mf++)
            ldm_x4(a_base + mf * 16 * RSB + kk * 32, ah[mf]);
        uint32_t b0[4], b1[4];
        ldm_x4(b_base + kk * 32,      b0);
        ldm_x4(b_base + kk * 32 + 16, b1);

#pragma unroll
        for (int mi = 0; mi < 4; mi++)
#pragma unroll
            for (int ni = 0; ni < 4; ni++)
                mma16816(acc[mi][ni], ah[mi], b0[ni], b1[ni]);
    }
}

// ================= GEMM 1: H = relu(Xg @ W1t[e] + b1[e]) -> fp16 =================
__global__ void __launch_bounds__(256, 2) k_gemm1(const float* __restrict__ b1) {
    int s = blockIdx.z;
    int cnt = (s == 0) ? NTOK : g_cnt[s];
    int m0 = blockIdx.x * 128;
    if (m0 >= cnt) return;
    int n0 = blockIdx.y * 128;

    extern __shared__ char smem[];
    uint32_t sb = smem_u32(smem);
    int t = threadIdx.x;
    int wid = t >> 5, lane = t & 31;
    int wm = wid >> 2, wn = wid & 3;
    int* toks = (int*)smem;

    if (t < 128) {
        int m = m0 + t;
        toks[t] = (m < cnt) ? ((s == 0) ? m : g_list[s * NTOK + m]) : 0;
    }
    __syncthreads();

    auto load_chunk = [&](int st, int k0) {
        uint32_t base = sb + SM_TILES + st * STAGE_BYTES;
#pragma unroll
        for (int i = 0; i < 2; i++) {
            int id = i * 256 + t;          // 0..511
            int row = id >> 2, seg = id & 3;
            uint32_t d = base + row * RSB + seg * 16;
            size_t aoff = (size_t)toks[row] * DDIM + k0 + seg * 8;
            cpa16(d + OFF_A, g_xa + aoff);
            size_t boff = ((size_t)s * HDIM + n0 + row) * DDIM + k0 + seg * 8;
            cpa16(d + OFF_B, g_w1 + boff);
        }
        CPA_COMMIT();
    };

    float acc[4][4][4];
#pragma unroll
    for (int mi = 0; mi < 4; mi++)
#pragma unroll
        for (int ni = 0; ni < 4; ni++)
#pragma unroll
            for (int q = 0; q < 4; q++) acc[mi][ni][q] = 0.f;

    load_chunk(0, 0);
    const int CH = DDIM / 32;   // 16
    for (int c = 0; c < CH; c++) {
        CPA_WAIT0();
        __syncthreads();
        if (c + 1 < CH) load_chunk((c + 1) & 1, (c + 1) * 32);
        gemm_compute_chunk(sb + SM_TILES + (c & 1) * STAGE_BYTES, wm, wn, lane, acc);
    }

    // epilogue: bias + relu -> fp16
    const float* bp = b1 + (size_t)s * HDIM;
#pragma unroll
    for (int mi = 0; mi < 4; mi++) {
        int mA = m0 + wm * 64 + mi * 16 + (lane >> 2);
        int mB = mA + 8;
        size_t rA = ((size_t)s * NTOK + mA) * HDIM;
        size_t rB = ((size_t)s * NTOK + mB) * HDIM;
        bool vA = mA < cnt, vB = mB < cnt;
#pragma unroll
        for (int ni = 0; ni < 4; ni++) {
            int col = n0 + wn * 32 + ni * 8 + 2 * (lane & 3);
            float bc0 = __ldg(bp + col), bc1 = __ldg(bp + col + 1);
            if (vA) {
                float v0 = fmaxf(acc[mi][ni][0] + bc0, 0.f);
                float v1 = fmaxf(acc[mi][ni][1] + bc1, 0.f);
                *(uint32_t*)(g_ha + rA + col) = pack2h(__float2half(v0), __float2half(v1));
            }
            if (vB) {
                float v0 = fmaxf(acc[mi][ni][2] + bc0, 0.f);
                float v1 = fmaxf(acc[mi][ni][3] + bc1, 0.f);
                *(uint32_t*)(g_ha + rB + col) = pack2h(__float2half(v0), __float2half(v1));
            }
        }
    }
}

// ================= GEMM 2: Y = scale * (H @ W2t[e] + b2[e]) =================
__global__ void __launch_bounds__(256, 2) k_gemm2(const float* __restrict__ b2,
                                                  const float* __restrict__ fw) {
    int s = blockIdx.z;
    int cnt = (s == 0) ? NTOK : g_cnt[s];
    int m0 = blockIdx.x * 128;
    if (m0 >= cnt) return;
    int n0 = blockIdx.y * 128;

    extern __shared__ char smem[];
    uint32_t sb = smem_u32(smem);
    int t = threadIdx.x;
    int wid = t >> 5, lane = t & 31;
    int wm = wid >> 2, wn = wid & 3;
    float* scl = (float*)smem;

    if (t < 128) {
        int m = m0 + t;
        scl[t] = (m < cnt) ? ((s == 0) ? BETA_FIXED * fw[0] : g_scale[s * NTOK + m]) : 0.f;
    }
    __syncthreads();

    auto load_chunk = [&](int st, int k0) {
        uint32_t base = sb + SM_TILES + st * STAGE_BYTES;
#pragma unroll
        for (int i = 0; i < 2; i++) {
            int id = i * 256 + t;
            int row = id >> 2, seg = id & 3;
            uint32_t d = base + row * RSB + seg * 16;
            size_t aoff = ((size_t)s * NTOK + m0 + row) * HDIM + k0 + seg * 8;
            cpa16(d + OFF_A, g_ha + aoff);
            size_t boff = ((size_t)s * DDIM + n0 + row) * HDIM + k0 + seg * 8;
            cpa16(d + OFF_B, g_w2 + boff);
        }
        CPA_COMMIT();
    };

    float acc[4][4][4];
#pragma unroll
    for (int mi = 0; mi < 4; mi++)
#pragma unroll
        for (int ni = 0; ni < 4; ni++)
#pragma unroll
            for (int q = 0; q < 4; q++) acc[mi][ni][q] = 0.f;

    load_chunk(0, 0);
    const int CH = HDIM / 32;   // 64
    for (int c = 0; c < CH; c++) {
        CPA_WAIT0();
        __syncthreads();
        if (c + 1 < CH) load_chunk((c + 1) & 1, (c + 1) * 32);
        gemm_compute_chunk(sb + SM_TILES + (c & 1) * STAGE_BYTES, wm, wn, lane, acc);
    }

    // epilogue: (acc + bias) * scale, fp32 store
    const float* bp = b2 + (size_t)s * DDIM;
#pragma unroll
    for (int mi = 0; mi < 4; mi++) {
        int mloc = wm * 64 + mi * 16 + (lane >> 2);
        int mA = m0 + mloc, mB = mA + 8;
        float scA = scl[mloc], scB = scl[mloc + 8];
        size_t rA = ((size_t)s * NTOK + mA) * DDIM;
        size_t rB = ((size_t)s * NTOK + mB) * DDIM;
        bool vA = mA < cnt, vB = mB < cnt;
#pragma unroll
        for (int ni = 0; ni < 4; ni++) {
            int col = n0 + wn * 32 + ni * 8 + 2 * (lane & 3);
            float bc0 = __ldg(bp + col), bc1 = __ldg(bp + col + 1);
            if (vA) {
                float2 v;
                v.x = (acc[mi][ni][0] + bc0) * scA;
                v.y = (acc[mi][ni][1] + bc1) * scA;
                *(float2*)(g_Y + rA + col) = v;
            }
            if (vB) {
                float2 v;
                v.x = (acc[mi][ni][2] + bc0) * scB;
                v.y = (acc[mi][ni][3] + bc1) * scB;
                *(float2*)(g_Y + rB + col) = v;
            }
        }
    }
}

// ================= combine =================
__global__ void k_combine(float* __restrict__ out) {
    int n = blockIdx.x;
    int t = threadIdx.x;
    const float4* y0 = (const float4*)(g_Y + (size_t)n * DDIM);
    int pA = g_pos[2 * n], pB = g_pos[2 * n + 1];
    const float4* yA = (const float4*)(g_Y + (size_t)pA * DDIM);
    const float4* yB = (const float4*)(g_Y + (size_t)pB * DDIM);
    float4 a = y0[t], b = yA[t], c = yB[t];
    float4 r;
    r.x = a.x + b.x + c.x;
    r.y = a.y + b.y + c.y;
    r.z = a.z + b.z + c.z;
    r.w = a.w + b.w + c.w;
    ((float4*)(out + (size_t)n * DDIM))[t] = r;
}

// ================= launch =================
extern "C" void kernel_launch(void* const* d_in, const int* in_sizes, int n_in,
                              void* d_out, int out_size) {
    const float* x  = (const float*)d_in[0];
    const float* rW = (const float*)d_in[1];
    const float* rb = (const float*)d_in[2];
    const float* W1 = (const float*)d_in[3];
    const float* b1 = (const float*)d_in[4];
    const float* W2 = (const float*)d_in[5];
    const float* b2 = (const float*)d_in[6];
    const float* fw = (const float*)d_in[7];
    float* out = (float*)d_out;
    long osz = (long)out_size;

    cudaFuncSetAttribute(k_gemm1, cudaFuncAttributeMaxDynamicSharedMemorySize, SMEM_BYTES);
    cudaFuncSetAttribute(k_gemm2, cudaFuncAttributeMaxDynamicSharedMemorySize, SMEM_BYTES);

    k_init<<<1, 32>>>();
    k_router<<<NTOK / 8, 256>>>(x, rW, rb, out, osz);
    k_aux<<<1, 1>>>(out, osz);
    k_cvt_x<<<(NTOK * DDIM / 4) / 256, 256>>>((const float4*)x);
    k_cvt_tr<<<dim3(HDIM / 32, DDIM / 32, NEXP), dim3(32, 8)>>>(W1, DDIM, HDIM, 0);
    k_cvt_tr<<<dim3(DDIM / 32, HDIM / 32, NEXP), dim3(32, 8)>>>(W2, HDIM, DDIM, 1);
    k_gemm1<<<dim3(32, 16, 8), 256, SMEM_BYTES>>>(b1);
    k_gemm2<<<dim3(32, 4, 8), 256, SMEM_BYTES>>>(b2, fw);
    k_combine<<<NTOK, 128>>>(out);
}